// round 14
// baseline (speedup 1.0000x reference)
#include <cuda_runtime.h>
#include <cstdint>
#include <cstddef>

#define NN 20000
#define DEG 16

// ---------------- scratch (static device globals; no allocation) ----------------
__device__ int   g_mask0[NN];
__device__ int   g_mask1[NN];
__device__ int   g_mask2[NN];
__device__ int   g_list0[4928];
__device__ int   g_list1[320];
__device__ int   g_list2[32];
__device__ int   g_cnt[4] = {0, 0, 0, 1};
__device__ float g_logits[NN];
__device__ float g_hN[320 * 1024];
__device__ float g_lpart[8 * 4992];            // logits per-Ntile partials
__device__ float g_partT[8 * 3 * 128 * 512];   // mma linear split-K partials
__device__ float g_wt0[512 * 1024];            // aw0^T [dh][din]
__device__ float g_wtL[512 * 2048];            // lw0^T [dh][2*din]
__device__ float g_wt1[256 * 512];             // aw1^T
__device__ float g_wtL1[256 * 1024];           // lw1^T
__device__ float g_h1[(size_t)NN * 512];
__device__ float g_h2[(size_t)NN * 256];

// ---------------- helpers ----------------
__device__ __forceinline__ uint32_t f2tf32(float f) {
    uint32_t r;
    asm("cvt.rna.tf32.f32 %0, %1;" : "=r"(r) : "f"(f));
    return r;
}
__device__ __forceinline__ void mma16x8x8(float* d, const uint32_t* a, const uint32_t* b) {
    asm volatile(
        "mma.sync.aligned.m16n8k8.row.col.f32.tf32.tf32.f32 "
        "{%0,%1,%2,%3}, {%4,%5,%6,%7}, {%8,%9}, {%0,%1,%2,%3};"
        : "+f"(d[0]), "+f"(d[1]), "+f"(d[2]), "+f"(d[3])
        : "r"(a[0]), "r"(a[1]), "r"(a[2]), "r"(a[3]), "r"(b[0]), "r"(b[1]));
}

// ---------------- cone construction (self-cleaning: masks restored to 0) -------
__global__ void cone_kernel(const int* __restrict__ senders) {
    const int tid = threadIdx.x;
    const int B = blockDim.x;
    if (tid < 3) g_cnt[tid] = 0;
    __syncthreads();
    if (tid < 17) {
        int s = (tid < 16) ? senders[14 * DEG + tid] : 14;
        if (atomicExch(&g_mask2[s], 1) == 0) g_list2[atomicAdd(&g_cnt[2], 1)] = s;
    }
    __syncthreads();
    int c2 = g_cnt[2];
    for (int t = tid; t < c2 * 17; t += B) {
        int i = t / 17, k = t - i * 17;
        int node = g_list2[i];
        int s = (k < 16) ? senders[node * DEG + k] : node;
        if (atomicExch(&g_mask1[s], 1) == 0) g_list1[atomicAdd(&g_cnt[1], 1)] = s;
    }
    __syncthreads();
    int c1 = g_cnt[1];
    for (int t = tid; t < c1 * 17; t += B) {
        int i = t / 17, k = t - i * 17;
        int node = g_list1[i];
        int s = (k < 16) ? senders[node * DEG + k] : node;
        if (atomicExch(&g_mask0[s], 1) == 0) g_list0[atomicAdd(&g_cnt[0], 1)] = s;
    }
    __syncthreads();
    int c0 = g_cnt[0];
    for (int t = tid; t < c0; t += B) g_mask0[g_list0[t]] = 0;
    for (int t = tid; t < c1; t += B) g_mask1[g_list1[t]] = 0;
    for (int t = tid; t < c2; t += B) g_mask2[g_list2[t]] = 0;
}

// ---------------- merged weight transposes: dst[n][k] = src[k][n] ----------------
__global__ void transpose_all_kernel(const float* __restrict__ aw0,
                                     const float* __restrict__ lw0,
                                     const float* __restrict__ aw1,
                                     const float* __restrict__ lw1) {
    const float* src; float* dst; int K, N;
    switch (blockIdx.z) {
        case 0:  src = aw0; dst = g_wt0;  K = 1024; N = 512; break;
        case 1:  src = lw0; dst = g_wtL;  K = 2048; N = 512; break;
        case 2:  src = aw1; dst = g_wt1;  K = 512;  N = 256; break;
        default: src = lw1; dst = g_wtL1; K = 1024; N = 256; break;
    }
    int k0 = blockIdx.x * 32, n0 = blockIdx.y * 32;
    if (k0 >= K || n0 >= N) return;
    __shared__ float t[32][33];
    int x = threadIdx.x, y = threadIdx.y;
    #pragma unroll
    for (int j = 0; j < 32; j += 8)
        t[y + j][x] = src[(size_t)(k0 + y + j) * N + n0 + x];
    __syncthreads();
    #pragma unroll
    for (int j = 0; j < 32; j += 8)
        dst[(size_t)(n0 + y + j) * K + k0 + x] = t[x][y + j];
}

// ---------------- mma.sync tf32 GEMM (512 threads, 16 warps, warp tile 16x64) --
// Tile: M=128, N=128, K-chunk=32. Same smem layout/bytes/prefetch as the proven
// 256-thread version; doubled warp count (4/SMSP) to hide LDS/issue latency.
// MODE 0 (logits): epilogue -> aq.relu partial per N-tile into lpart[ntile*4992+m].
// MODE 1 (linear): raw D partials into outBuf[((z*MT+bx)*128+r)*DH + n0+c].
#define ASTR 36

template <int MODE>
__global__ __launch_bounds__(512, 1)
void mma_gemm_kernel(const float* __restrict__ X,
                     const float* __restrict__ hN,
                     const float* __restrict__ wt,
                     const float* __restrict__ aq,
                     float* __restrict__ outBuf,
                     const int* __restrict__ list,
                     const int* __restrict__ cntPtr,
                     int din, int Ktot, int kPerSplit, int MT, int DH) {
    __shared__ uint32_t As[128 * ASTR];
    __shared__ uint32_t Bs[128 * ASTR];
    __shared__ int snode[128];
    __shared__ float sred[128];
    __shared__ float saq[128];

    const int tid = threadIdx.x;
    const int w = tid >> 5, lane = tid & 31;
    const int g = lane >> 2, t4 = lane & 3;
    const int wm = w >> 1, wn = w & 1;          // wm 0..7 (16 rows each), wn 0..1 (64 cols)
    const int cnt = *cntPtr;
    const int m0 = blockIdx.x * 128;
    if (m0 >= cnt) return;
    const int n0 = blockIdx.y * 128;
    const int kBase = blockIdx.z * kPerSplit;
    const int nch = kPerSplit / 32;

    if (tid < 128) {
        int p = m0 + tid; if (p >= cnt) p = cnt - 1;
        snode[tid] = list[p];
        if (MODE == 0) saq[tid] = aq[n0 + tid];
    }
    __syncthreads();

    float acc[8][4];
    #pragma unroll
    for (int nf = 0; nf < 8; nf++)
        #pragma unroll
        for (int e = 0; e < 4; e++) acc[nf][e] = 0.f;

    float4 ra[2], rb[2];
    auto loadChunk = [&](int c) {
        const int k0 = kBase + c * 32;
        #pragma unroll
        for (int j = 0; j < 2; j++) {
            int i = j * 512 + tid;
            int row = i >> 3, col = (i & 7) * 4;
            const float* srcA;
            if (MODE == 0) {
                srcA = X + (size_t)snode[row] * din + k0 + col;
            } else {
                int d = k0 + col;
                if (d < din) srcA = X + (size_t)snode[row] * din + d;
                else {
                    int p = m0 + row; if (p >= cnt) p = cnt - 1;
                    srcA = hN + (size_t)p * din + (d - din);
                }
            }
            ra[j] = *reinterpret_cast<const float4*>(srcA);
            rb[j] = *reinterpret_cast<const float4*>(
                wt + (size_t)(n0 + row) * Ktot + k0 + col);
        }
    };
    auto stageChunk = [&]() {
        #pragma unroll
        for (int j = 0; j < 2; j++) {
            int i = j * 512 + tid;
            int row = i >> 3, col = (i & 7) * 4;
            uint4 va = make_uint4(f2tf32(ra[j].x), f2tf32(ra[j].y),
                                  f2tf32(ra[j].z), f2tf32(ra[j].w));
            uint4 vb = make_uint4(f2tf32(rb[j].x), f2tf32(rb[j].y),
                                  f2tf32(rb[j].z), f2tf32(rb[j].w));
            *reinterpret_cast<uint4*>(&As[row * ASTR + col]) = va;
            *reinterpret_cast<uint4*>(&Bs[row * ASTR + col]) = vb;
        }
    };

    loadChunk(0);
    for (int c = 0; c < nch; c++) {
        stageChunk();
        __syncthreads();
        if (c + 1 < nch) loadChunk(c + 1);

        #pragma unroll
        for (int ks = 0; ks < 4; ks++) {
            const int k0 = ks * 8;
            const int r = wm * 16 + g;
            uint32_t af[4];
            af[0] = As[r * ASTR + k0 + t4];
            af[1] = As[(r + 8) * ASTR + k0 + t4];
            af[2] = As[r * ASTR + k0 + t4 + 4];
            af[3] = As[(r + 8) * ASTR + k0 + t4 + 4];
            #pragma unroll
            for (int nf = 0; nf < 8; nf++) {
                int cN = wn * 64 + nf * 8 + g;
                uint32_t bf[2];
                bf[0] = Bs[cN * ASTR + k0 + t4];
                bf[1] = Bs[cN * ASTR + k0 + t4 + 4];
                mma16x8x8(acc[nf], af, bf);
            }
        }
        __syncthreads();
    }

    if (MODE == 0) {
        float s[2] = {0.f, 0.f};
        #pragma unroll
        for (int nf = 0; nf < 8; nf++) {
            int c0 = wn * 64 + nf * 8 + t4 * 2;
            float a0 = saq[c0], a1 = saq[c0 + 1];
            s[0] += a0 * fmaxf(acc[nf][0], 0.f) + a1 * fmaxf(acc[nf][1], 0.f);
            s[1] += a0 * fmaxf(acc[nf][2], 0.f) + a1 * fmaxf(acc[nf][3], 0.f);
        }
        #pragma unroll
        for (int h = 0; h < 2; h++) {
            s[h] += __shfl_xor_sync(0xffffffffu, s[h], 1);
            s[h] += __shfl_xor_sync(0xffffffffu, s[h], 2);
        }
        if (wn == 0 && t4 == 0) {
            sred[wm * 16 + g]     = s[0];
            sred[wm * 16 + 8 + g] = s[1];
        }
        __syncthreads();
        if (wn == 1 && t4 == 0) {
            sred[wm * 16 + g]     += s[0];
            sred[wm * 16 + 8 + g] += s[1];
        }
        __syncthreads();
        if (tid < 128)
            outBuf[blockIdx.y * 4992 + m0 + tid] = sred[tid];
    } else {
        const int bx = blockIdx.x, z = blockIdx.z;
        const int r0 = wm * 16 + g;
        #pragma unroll
        for (int nf = 0; nf < 8; nf++) {
            int c0 = n0 + wn * 64 + nf * 8 + t4 * 2;
            size_t b0 = ((size_t)(z * MT + bx) * 128 + r0) * DH + c0;
            size_t b1 = ((size_t)(z * MT + bx) * 128 + r0 + 8) * DH + c0;
            *reinterpret_cast<float2*>(&outBuf[b0]) = make_float2(acc[nf][0], acc[nf][1]);
            *reinterpret_cast<float2*>(&outBuf[b1]) = make_float2(acc[nf][2], acc[nf][3]);
        }
    }
}

// ---------------- reduces for the tensor path ----------------
__global__ void logits_reduce_kernel(const float* __restrict__ lpart,
                                     float* __restrict__ logits,
                                     const int* __restrict__ list,
                                     const int* __restrict__ cntPtr,
                                     int nt) {
    int i = blockIdx.x * blockDim.x + threadIdx.x;
    if (i >= *cntPtr) return;
    float s = 0.f;
    for (int n = 0; n < nt; n++) s += lpart[n * 4992 + i];
    logits[list[i]] = s;
}

__global__ void tlinear_reduce_kernel(const float* __restrict__ part,
                                      const float* __restrict__ lb,
                                      float* __restrict__ hout,
                                      const int* __restrict__ list,
                                      const int* __restrict__ cntPtr,
                                      int nz, int MT, int DH) {
    int pos = blockIdx.x;
    if (pos >= *cntPtr) return;
    int node = list[pos];
    int mt = pos >> 7, row = pos & 127;
    for (int col = threadIdx.x; col < DH; col += blockDim.x) {
        float s = lb[col];
        for (int z = 0; z < nz; z++)
            s += part[((size_t)(z * MT + mt) * 128 + row) * DH + col];
        hout[(size_t)node * DH + col] = fmaxf(s, 0.f);
    }
}

// ---------------- softmax over 16 neighbors + weighted message ----------------
__global__ void attn_kernel(const float* __restrict__ hin,
                            const float* __restrict__ logits,
                            const int* __restrict__ senders,
                            const int* __restrict__ list,
                            const int* __restrict__ cntPtr,
                            float* __restrict__ hN, int din) {
    int pos = blockIdx.x;
    if (pos >= *cntPtr) return;
    int node = list[pos];
    int tid = threadIdx.x;

    __shared__ int   ss[16];
    __shared__ float sw[16];
    __shared__ float sinv;
    if (tid < 32) {
        float el = -1e30f;
        int s = 0;
        if (tid < 16) { s = senders[node * DEG + tid]; el = logits[s]; ss[tid] = s; }
        float m = el;
        #pragma unroll
        for (int off = 8; off > 0; off >>= 1) m = fmaxf(m, __shfl_xor_sync(0xffffffffu, m, off));
        float w = (tid < 16) ? expf(el - m) : 0.f;
        float sum = w;
        #pragma unroll
        for (int off = 8; off > 0; off >>= 1) sum += __shfl_xor_sync(0xffffffffu, sum, off);
        if (tid < 16) sw[tid] = w;
        if (tid == 0) sinv = 1.f / sum;
    }
    __syncthreads();
    float inv = sinv;
    int nd4 = din >> 2;
    int stride = blockDim.x * gridDim.y;
    for (int d4 = blockIdx.y * blockDim.x + tid; d4 < nd4; d4 += stride) {
        float4 m = make_float4(0.f, 0.f, 0.f, 0.f);
        #pragma unroll
        for (int k = 0; k < 16; k++) {
            float4 x = *reinterpret_cast<const float4*>(&hin[(size_t)ss[k] * din + d4 * 4]);
            float wk = sw[k];
            m.x = fmaf(wk, x.x, m.x);
            m.y = fmaf(wk, x.y, m.y);
            m.z = fmaf(wk, x.z, m.z);
            m.w = fmaf(wk, x.w, m.w);
        }
        m.x *= inv; m.y *= inv; m.z *= inv; m.w *= inv;
        *reinterpret_cast<float4*>(&hN[(size_t)pos * din + d4 * 4]) = m;
    }
}

// ---------------- fused layer 2 + output head (one block, 256 threads) ---------
__global__ void layer2_out_kernel(const int* __restrict__ senders,
                                  const float* __restrict__ aw2,
                                  const float* __restrict__ aq2,
                                  const float* __restrict__ lw2,
                                  const float* __restrict__ lb2,
                                  const float* __restrict__ ow,
                                  const float* __restrict__ ob,
                                  float* __restrict__ out) {
    __shared__ float hs[17][256];
    __shared__ float slog[17];
    __shared__ int   spos[16];
    __shared__ float sw[16];
    __shared__ float sinv;
    __shared__ int   spos14;
    __shared__ float smsg[256];
    __shared__ float sh3[128];

    const int tid = threadIdx.x;
    const int w = tid >> 5, lane = tid & 31;
    const int cnt2 = g_cnt[2];

    for (int idx = tid; idx < cnt2 * 256; idx += 256) {
        int j = idx >> 8, d = idx & 255;
        hs[j][d] = g_h2[(size_t)g_list2[j] * 256 + d];
    }
    if (tid < cnt2 && g_list2[tid] == 14) spos14 = tid;
    __syncthreads();

    for (int j = w; j < cnt2; j += 8) {
        float4 acc = make_float4(0.f, 0.f, 0.f, 0.f);
        for (int k = 0; k < 256; k++) {
            float h = hs[j][k];
            float4 wt = *reinterpret_cast<const float4*>(&aw2[k * 128 + lane * 4]);
            acc.x = fmaf(h, wt.x, acc.x);
            acc.y = fmaf(h, wt.y, acc.y);
            acc.z = fmaf(h, wt.z, acc.z);
            acc.w = fmaf(h, wt.w, acc.w);
        }
        float4 a = *reinterpret_cast<const float4*>(&aq2[lane * 4]);
        float s = a.x * fmaxf(acc.x, 0.f) + a.y * fmaxf(acc.y, 0.f)
                + a.z * fmaxf(acc.z, 0.f) + a.w * fmaxf(acc.w, 0.f);
        #pragma unroll
        for (int off = 16; off > 0; off >>= 1)
            s += __shfl_xor_sync(0xffffffffu, s, off);
        if (lane == 0) slog[j] = s;
    }
    __syncthreads();

    if (w == 0) {
        float el = -1e30f;
        int p = 0;
        if (lane < 16) {
            int s = senders[14 * DEG + lane];
            for (int j = 0; j < cnt2; j++) if (g_list2[j] == s) p = j;
            el = slog[p];
            spos[lane] = p;
        }
        float m = el;
        #pragma unroll
        for (int off = 8; off > 0; off >>= 1)
            m = fmaxf(m, __shfl_xor_sync(0xffffffffu, m, off));
        float wv = (lane < 16) ? expf(el - m) : 0.f;
        float sum = wv;
        #pragma unroll
        for (int off = 8; off > 0; off >>= 1)
            sum += __shfl_xor_sync(0xffffffffu, sum, off);
        if (lane < 16) sw[lane] = wv;
        if (lane == 0) sinv = 1.f / sum;
    }
    __syncthreads();

    {
        float m = 0.f;
        #pragma unroll
        for (int k = 0; k < 16; k++) m = fmaf(sw[k], hs[spos[k]][tid], m);
        smsg[tid] = m * sinv;
    }
    __syncthreads();

    if (tid < 128) {
        float acc = lb2[tid];
        for (int k = 0; k < 256; k++) acc = fmaf(hs[spos14][k], lw2[k * 128 + tid], acc);
        for (int k = 0; k < 256; k++) acc = fmaf(smsg[k], lw2[(256 + k) * 128 + tid], acc);
        sh3[tid] = fmaxf(acc, 0.f);
    }
    __syncthreads();

    if (tid < 128) {
        float acc = ob[tid];
        #pragma unroll 8
        for (int d = 0; d < 128; d++) acc = fmaf(sh3[d], ow[d * 128 + tid], acc);
        out[tid] = acc;
    }
}

// ---------------- launch ----------------
extern "C" void kernel_launch(void* const* d_in, const int* in_sizes, int n_in,
                              void* d_out, int out_size) {
    const float* X       = (const float*)d_in[0];
    const int*   senders = (const int*)d_in[1];
    const float* lw0 = (const float*)d_in[3];
    const float* lb0 = (const float*)d_in[4];
    const float* aw0 = (const float*)d_in[5];
    const float* aq0 = (const float*)d_in[6];
    const float* lw1 = (const float*)d_in[7];
    const float* lb1 = (const float*)d_in[8];
    const float* aw1 = (const float*)d_in[9];
    const float* aq1 = (const float*)d_in[10];
    const float* lw2 = (const float*)d_in[11];
    const float* lb2 = (const float*)d_in[12];
    const float* aw2 = (const float*)d_in[13];
    const float* aq2 = (const float*)d_in[14];
    const float* ow  = (const float*)d_in[15];
    const float* ob  = (const float*)d_in[16];

    int *l0, *l1, *l2, *cnt;
    float *logits, *hN, *lpart, *partT, *wt0, *wtL, *wt1, *wtL1, *h1, *h2;
    cudaGetSymbolAddress((void**)&l0, g_list0);
    cudaGetSymbolAddress((void**)&l1, g_list1);
    cudaGetSymbolAddress((void**)&l2, g_list2);
    cudaGetSymbolAddress((void**)&cnt, g_cnt);
    cudaGetSymbolAddress((void**)&logits, g_logits);
    cudaGetSymbolAddress((void**)&hN, g_hN);
    cudaGetSymbolAddress((void**)&lpart, g_lpart);
    cudaGetSymbolAddress((void**)&partT, g_partT);
    cudaGetSymbolAddress((void**)&wt0, g_wt0);
    cudaGetSymbolAddress((void**)&wtL, g_wtL);
    cudaGetSymbolAddress((void**)&wt1, g_wt1);
    cudaGetSymbolAddress((void**)&wtL1, g_wtL1);
    cudaGetSymbolAddress((void**)&h1, g_h1);
    cudaGetSymbolAddress((void**)&h2, g_h2);

    cone_kernel<<<1, 1024>>>(senders);
    transpose_all_kernel<<<dim3(64, 16, 4), dim3(32, 8)>>>(aw0, lw0, aw1, lw1);

    // ---- layer 0: tf32 mma.sync (din=1024, dh=512) ----
    mma_gemm_kernel<0><<<dim3(39, 4, 1), 512>>>(
        X, nullptr, wt0, aq0, lpart, l0, cnt + 0, 1024, 1024, 1024, 0, 0);
    logits_reduce_kernel<<<20, 256>>>(lpart, logits, l0, cnt + 0, 4);
    attn_kernel<<<dim3(289, 4), 256>>>(X, logits, senders, l1, cnt + 1, hN, 1024);
    mma_gemm_kernel<1><<<dim3(3, 4, 8), 512>>>(
        X, hN, wtL, nullptr, partT, l1, cnt + 1, 1024, 2048, 256, 3, 512);
    tlinear_reduce_kernel<<<289, 256>>>(partT, lb0, h1, l1, cnt + 1, 8, 3, 512);

    // ---- layer 1: tf32 mma.sync (din=512, dh=256) ----
    mma_gemm_kernel<0><<<dim3(3, 2, 1), 512>>>(
        h1, nullptr, wt1, aq1, lpart, l1, cnt + 1, 512, 512, 512, 0, 0);
    logits_reduce_kernel<<<2, 256>>>(lpart, logits, l1, cnt + 1, 2);
    attn_kernel<<<dim3(17, 2), 256>>>(h1, logits, senders, l2, cnt + 2, hN, 512);
    mma_gemm_kernel<1><<<dim3(1, 2, 2), 512>>>(
        h1, hN, wtL1, nullptr, partT, l2, cnt + 2, 512, 1024, 512, 1, 256);
    tlinear_reduce_kernel<<<17, 256>>>(partT, lb1, h2, l2, cnt + 2, 2, 1, 256);

    // ---- layer 2 + output head: fully fused, one block ----
    layer2_out_kernel<<<1, 256>>>(senders, aw2, aq2, lw2, lb2, ow, ob, (float*)d_out);
}

// round 16
// speedup vs baseline: 1.1058x; 1.1058x over previous
#include <cuda_runtime.h>
#include <cstdint>
#include <cstddef>

#define NN 20000
#define DEG 16

// ---------------- scratch (static device globals; no allocation) ----------------
__device__ int   g_mask0[NN];
__device__ int   g_mask1[NN];
__device__ int   g_mask2[NN];
__device__ int   g_pos0[NN];                   // node -> position in list0 (valid for cone nodes)
__device__ int   g_pos1[NN];                   // node -> position in list1
__device__ int   g_list0[4928];
__device__ int   g_list1[320];
__device__ int   g_list2[32];
__device__ int   g_cnt[4] = {0, 0, 0, 1};
__device__ float g_hN[320 * 1024];
__device__ float g_lpart[8 * 4992];            // logits per-Ntile partials
__device__ float g_partT[8 * 3 * 128 * 512];   // mma linear split-K partials
__device__ float g_wt0[512 * 1024];            // aw0^T [dh][din]
__device__ float g_wtL[512 * 2048];            // lw0^T [dh][2*din]
__device__ float g_wt1[256 * 512];             // aw1^T
__device__ float g_wtL1[256 * 1024];           // lw1^T
__device__ float g_h1[(size_t)NN * 512];

// ---------------- helpers ----------------
__device__ __forceinline__ uint32_t f2tf32(float f) {
    uint32_t r;
    asm("cvt.rna.tf32.f32 %0, %1;" : "=r"(r) : "f"(f));
    return r;
}
__device__ __forceinline__ void mma16x8x8(float* d, const uint32_t* a, const uint32_t* b) {
    asm volatile(
        "mma.sync.aligned.m16n8k8.row.col.f32.tf32.tf32.f32 "
        "{%0,%1,%2,%3}, {%4,%5,%6,%7}, {%8,%9}, {%0,%1,%2,%3};"
        : "+f"(d[0]), "+f"(d[1]), "+f"(d[2]), "+f"(d[3])
        : "r"(a[0]), "r"(a[1]), "r"(a[2]), "r"(a[3]), "r"(b[0]), "r"(b[1]));
}

// ---------------- cone construction (self-cleaning; writes position maps) -------
__global__ void cone_kernel(const int* __restrict__ senders) {
    const int tid = threadIdx.x;
    const int B = blockDim.x;
    if (tid < 3) g_cnt[tid] = 0;
    __syncthreads();
    if (tid < 17) {
        int s = (tid < 16) ? senders[14 * DEG + tid] : 14;
        if (atomicExch(&g_mask2[s], 1) == 0) g_list2[atomicAdd(&g_cnt[2], 1)] = s;
    }
    __syncthreads();
    int c2 = g_cnt[2];
    for (int t = tid; t < c2 * 17; t += B) {
        int i = t / 17, k = t - i * 17;
        int node = g_list2[i];
        int s = (k < 16) ? senders[node * DEG + k] : node;
        if (atomicExch(&g_mask1[s], 1) == 0) g_list1[atomicAdd(&g_cnt[1], 1)] = s;
    }
    __syncthreads();
    int c1 = g_cnt[1];
    for (int t = tid; t < c1 * 17; t += B) {
        int i = t / 17, k = t - i * 17;
        int node = g_list1[i];
        int s = (k < 16) ? senders[node * DEG + k] : node;
        if (atomicExch(&g_mask0[s], 1) == 0) g_list0[atomicAdd(&g_cnt[0], 1)] = s;
    }
    __syncthreads();
    int c0 = g_cnt[0];
    // position maps (overwritten before use every replay; only cone nodes are read)
    for (int t = tid; t < c0; t += B) { g_pos0[g_list0[t]] = t; g_mask0[g_list0[t]] = 0; }
    for (int t = tid; t < c1; t += B) { g_pos1[g_list1[t]] = t; g_mask1[g_list1[t]] = 0; }
    for (int t = tid; t < c2; t += B) g_mask2[g_list2[t]] = 0;
}

// ---------------- merged weight transposes: dst[n][k] = src[k][n] ----------------
__global__ void transpose_all_kernel(const float* __restrict__ aw0,
                                     const float* __restrict__ lw0,
                                     const float* __restrict__ aw1,
                                     const float* __restrict__ lw1) {
    const float* src; float* dst; int K, N;
    switch (blockIdx.z) {
        case 0:  src = aw0; dst = g_wt0;  K = 1024; N = 512; break;
        case 1:  src = lw0; dst = g_wtL;  K = 2048; N = 512; break;
        case 2:  src = aw1; dst = g_wt1;  K = 512;  N = 256; break;
        default: src = lw1; dst = g_wtL1; K = 1024; N = 256; break;
    }
    int k0 = blockIdx.x * 32, n0 = blockIdx.y * 32;
    if (k0 >= K || n0 >= N) return;
    __shared__ float t[32][33];
    int x = threadIdx.x, y = threadIdx.y;
    #pragma unroll
    for (int j = 0; j < 32; j += 8)
        t[y + j][x] = src[(size_t)(k0 + y + j) * N + n0 + x];
    __syncthreads();
    #pragma unroll
    for (int j = 0; j < 32; j += 8)
        dst[(size_t)(n0 + y + j) * K + k0 + x] = t[x][y + j];
}

// ---------------- mma.sync tf32 GEMM (round-8 proven version, byte-identical) --
// Tile: M=128, N=128, K-chunk=32. 256 threads = 8 warps, warp tile 32x64.
// MODE 0 (logits): epilogue -> aq.relu partial per N-tile into lpart[ntile*4992+m].
// MODE 1 (linear): raw D partials into outBuf[((z*MT+bx)*128+r)*DH + n0+c].
#define ASTR 36

template <int MODE>
__global__ __launch_bounds__(256, 1)
void mma_gemm_kernel(const float* __restrict__ X,
                     const float* __restrict__ hN,
                     const float* __restrict__ wt,
                     const float* __restrict__ aq,
                     float* __restrict__ outBuf,
                     const int* __restrict__ list,
                     const int* __restrict__ cntPtr,
                     int din, int Ktot, int kPerSplit, int MT, int DH) {
    __shared__ uint32_t As[128 * ASTR];
    __shared__ uint32_t Bs[128 * ASTR];
    __shared__ int snode[128];
    __shared__ float sred[128];
    __shared__ float saq[128];

    const int tid = threadIdx.x;
    const int w = tid >> 5, lane = tid & 31;
    const int g = lane >> 2, t4 = lane & 3;
    const int wm = w >> 1, wn = w & 1;
    const int cnt = *cntPtr;
    const int m0 = blockIdx.x * 128;
    if (m0 >= cnt) return;
    const int n0 = blockIdx.y * 128;
    const int kBase = blockIdx.z * kPerSplit;
    const int nch = kPerSplit / 32;

    if (tid < 128) {
        int p = m0 + tid; if (p >= cnt) p = cnt - 1;
        snode[tid] = list[p];
        if (MODE == 0) saq[tid] = aq[n0 + tid];
    }
    __syncthreads();

    float acc[2][8][4];
    #pragma unroll
    for (int mf = 0; mf < 2; mf++)
        #pragma unroll
        for (int nf = 0; nf < 8; nf++)
            #pragma unroll
            for (int e = 0; e < 4; e++) acc[mf][nf][e] = 0.f;

    float4 ra[4], rb[4];
    auto loadChunk = [&](int c) {
        const int k0 = kBase + c * 32;
        #pragma unroll
        for (int j = 0; j < 4; j++) {
            int i = j * 256 + tid;
            int row = i >> 3, col = (i & 7) * 4;
            const float* srcA;
            if (MODE == 0) {
                srcA = X + (size_t)snode[row] * din + k0 + col;
            } else {
                int d = k0 + col;
                if (d < din) srcA = X + (size_t)snode[row] * din + d;
                else {
                    int p = m0 + row; if (p >= cnt) p = cnt - 1;
                    srcA = hN + (size_t)p * din + (d - din);
                }
            }
            ra[j] = *reinterpret_cast<const float4*>(srcA);
            rb[j] = *reinterpret_cast<const float4*>(
                wt + (size_t)(n0 + row) * Ktot + k0 + col);
        }
    };
    auto stageChunk = [&]() {
        #pragma unroll
        for (int j = 0; j < 4; j++) {
            int i = j * 256 + tid;
            int row = i >> 3, col = (i & 7) * 4;
            uint4 va = make_uint4(f2tf32(ra[j].x), f2tf32(ra[j].y),
                                  f2tf32(ra[j].z), f2tf32(ra[j].w));
            uint4 vb = make_uint4(f2tf32(rb[j].x), f2tf32(rb[j].y),
                                  f2tf32(rb[j].z), f2tf32(rb[j].w));
            *reinterpret_cast<uint4*>(&As[row * ASTR + col]) = va;
            *reinterpret_cast<uint4*>(&Bs[row * ASTR + col]) = vb;
        }
    };

    loadChunk(0);
    for (int c = 0; c < nch; c++) {
        stageChunk();
        __syncthreads();
        if (c + 1 < nch) loadChunk(c + 1);

        #pragma unroll
        for (int ks = 0; ks < 4; ks++) {
            const int k0 = ks * 8;
            uint32_t af[2][4];
            #pragma unroll
            for (int mf = 0; mf < 2; mf++) {
                int r = wm * 32 + mf * 16 + g;
                af[mf][0] = As[r * ASTR + k0 + t4];
                af[mf][1] = As[(r + 8) * ASTR + k0 + t4];
                af[mf][2] = As[r * ASTR + k0 + t4 + 4];
                af[mf][3] = As[(r + 8) * ASTR + k0 + t4 + 4];
            }
            #pragma unroll
            for (int nf = 0; nf < 8; nf++) {
                int cN = wn * 64 + nf * 8 + g;
                uint32_t bf[2];
                bf[0] = Bs[cN * ASTR + k0 + t4];
                bf[1] = Bs[cN * ASTR + k0 + t4 + 4];
                mma16x8x8(acc[0][nf], af[0], bf);
                mma16x8x8(acc[1][nf], af[1], bf);
            }
        }
        __syncthreads();
    }

    if (MODE == 0) {
        float s[2][2] = {{0.f, 0.f}, {0.f, 0.f}};
        #pragma unroll
        for (int mf = 0; mf < 2; mf++)
            #pragma unroll
            for (int nf = 0; nf < 8; nf++) {
                int c0 = wn * 64 + nf * 8 + t4 * 2;
                float a0 = saq[c0], a1 = saq[c0 + 1];
                s[mf][0] += a0 * fmaxf(acc[mf][nf][0], 0.f) + a1 * fmaxf(acc[mf][nf][1], 0.f);
                s[mf][1] += a0 * fmaxf(acc[mf][nf][2], 0.f) + a1 * fmaxf(acc[mf][nf][3], 0.f);
            }
        #pragma unroll
        for (int mf = 0; mf < 2; mf++)
            #pragma unroll
            for (int h = 0; h < 2; h++) {
                s[mf][h] += __shfl_xor_sync(0xffffffffu, s[mf][h], 1);
                s[mf][h] += __shfl_xor_sync(0xffffffffu, s[mf][h], 2);
            }
        if (wn == 0 && t4 == 0) {
            #pragma unroll
            for (int mf = 0; mf < 2; mf++) {
                sred[wm * 32 + mf * 16 + g] = s[mf][0];
                sred[wm * 32 + mf * 16 + g + 8] = s[mf][1];
            }
        }
        __syncthreads();
        if (wn == 1 && t4 == 0) {
            #pragma unroll
            for (int mf = 0; mf < 2; mf++) {
                sred[wm * 32 + mf * 16 + g] += s[mf][0];
                sred[wm * 32 + mf * 16 + g + 8] += s[mf][1];
            }
        }
        __syncthreads();
        if (tid < 128)
            outBuf[blockIdx.y * 4992 + m0 + tid] = sred[tid];
    } else {
        const int bx = blockIdx.x, z = blockIdx.z;
        #pragma unroll
        for (int mf = 0; mf < 2; mf++) {
            int r0 = wm * 32 + mf * 16 + g;
            #pragma unroll
            for (int nf = 0; nf < 8; nf++) {
                int c0 = n0 + wn * 64 + nf * 8 + t4 * 2;
                size_t b0 = ((size_t)(z * MT + bx) * 128 + r0) * DH + c0;
                size_t b1 = ((size_t)(z * MT + bx) * 128 + r0 + 8) * DH + c0;
                *reinterpret_cast<float2*>(&outBuf[b0]) =
                    make_float2(acc[mf][nf][0], acc[mf][nf][1]);
                *reinterpret_cast<float2*>(&outBuf[b1]) =
                    make_float2(acc[mf][nf][2], acc[mf][nf][3]);
            }
        }
    }
}

// ---------------- tlinear reduce (layer 0 only now) ----------------
__global__ void tlinear_reduce_kernel(const float* __restrict__ part,
                                      const float* __restrict__ lb,
                                      float* __restrict__ hout,
                                      const int* __restrict__ list,
                                      const int* __restrict__ cntPtr,
                                      int nz, int MT, int DH) {
    int pos = blockIdx.x;
    if (pos >= *cntPtr) return;
    int node = list[pos];
    int mt = pos >> 7, row = pos & 127;
    for (int col = threadIdx.x; col < DH; col += blockDim.x) {
        float s = lb[col];
        for (int z = 0; z < nz; z++)
            s += part[((size_t)(z * MT + mt) * 128 + row) * DH + col];
        hout[(size_t)node * DH + col] = fmaxf(s, 0.f);
    }
}

// ---------------- attn (fused lpart reduce via position map) ----------------
// logit(s) = sum_{n<nt} lpart[n*4992 + posMap[s]]
__global__ void attn_kernel(const float* __restrict__ hin,
                            const float* __restrict__ lpart,
                            const int* __restrict__ posMap,
                            const int* __restrict__ senders,
                            const int* __restrict__ list,
                            const int* __restrict__ cntPtr,
                            float* __restrict__ hN, int din, int nt) {
    int pos = blockIdx.x;
    if (pos >= *cntPtr) return;
    int node = list[pos];
    int tid = threadIdx.x;

    __shared__ int   ss[16];
    __shared__ float sw[16];
    __shared__ float sinv;
    if (tid < 32) {
        float el = -1e30f;
        int s = 0;
        if (tid < 16) {
            s = senders[node * DEG + tid];
            int lp = posMap[s];
            el = 0.f;
            for (int n = 0; n < nt; n++) el += lpart[n * 4992 + lp];
            ss[tid] = s;
        }
        float m = el;
        #pragma unroll
        for (int off = 8; off > 0; off >>= 1) m = fmaxf(m, __shfl_xor_sync(0xffffffffu, m, off));
        float w = (tid < 16) ? expf(el - m) : 0.f;
        float sum = w;
        #pragma unroll
        for (int off = 8; off > 0; off >>= 1) sum += __shfl_xor_sync(0xffffffffu, sum, off);
        if (tid < 16) sw[tid] = w;
        if (tid == 0) sinv = 1.f / sum;
    }
    __syncthreads();
    float inv = sinv;
    int nd4 = din >> 2;
    int stride = blockDim.x * gridDim.y;
    for (int d4 = blockIdx.y * blockDim.x + tid; d4 < nd4; d4 += stride) {
        float4 m = make_float4(0.f, 0.f, 0.f, 0.f);
        #pragma unroll
        for (int k = 0; k < 16; k++) {
            float4 x = *reinterpret_cast<const float4*>(&hin[(size_t)ss[k] * din + d4 * 4]);
            float wk = sw[k];
            m.x = fmaf(wk, x.x, m.x);
            m.y = fmaf(wk, x.y, m.y);
            m.z = fmaf(wk, x.z, m.z);
            m.w = fmaf(wk, x.w, m.w);
        }
        m.x *= inv; m.y *= inv; m.z *= inv; m.w *= inv;
        *reinterpret_cast<float4*>(&hN[(size_t)pos * din + d4 * 4]) = m;
    }
}

// ---------------- fused tlinear_reduce1 + layer 2 + output head ----------------
// hs[j] = relu(lb1 + sum_z partT[(z*128+j)*256 + d]); then logits2, softmax,
// message, linear2, projection. One block, 256 threads.
__global__ void layer2_out_kernel(const float* __restrict__ partT,
                                  const float* __restrict__ lb1,
                                  const int* __restrict__ senders,
                                  const float* __restrict__ aw2,
                                  const float* __restrict__ aq2,
                                  const float* __restrict__ lw2,
                                  const float* __restrict__ lb2,
                                  const float* __restrict__ ow,
                                  const float* __restrict__ ob,
                                  float* __restrict__ out, int nz1) {
    __shared__ float hs[17][256];
    __shared__ float slog[17];
    __shared__ int   spos[16];
    __shared__ float sw[16];
    __shared__ float sinv;
    __shared__ int   spos14;
    __shared__ float smsg[256];
    __shared__ float sh3[128];

    const int tid = threadIdx.x;
    const int w = tid >> 5, lane = tid & 31;
    const int cnt2 = g_cnt[2];

    // stage layer-2 rows from partials: h2[pos j] = relu(lb1 + sum_z partT)
    for (int idx = tid; idx < cnt2 * 256; idx += 256) {
        int j = idx >> 8, d = idx & 255;
        float s = lb1[d];
        for (int z = 0; z < nz1; z++)
            s += partT[((size_t)z * 128 + j) * 256 + d];
        hs[j][d] = fmaxf(s, 0.f);
    }
    if (tid < cnt2 && g_list2[tid] == 14) spos14 = tid;
    __syncthreads();

    // logits2: warp per row; lane covers 4 of 128 cols
    for (int j = w; j < cnt2; j += 8) {
        float4 acc = make_float4(0.f, 0.f, 0.f, 0.f);
        for (int k = 0; k < 256; k++) {
            float h = hs[j][k];
            float4 wt = *reinterpret_cast<const float4*>(&aw2[k * 128 + lane * 4]);
            acc.x = fmaf(h, wt.x, acc.x);
            acc.y = fmaf(h, wt.y, acc.y);
            acc.z = fmaf(h, wt.z, acc.z);
            acc.w = fmaf(h, wt.w, acc.w);
        }
        float4 a = *reinterpret_cast<const float4*>(&aq2[lane * 4]);
        float s = a.x * fmaxf(acc.x, 0.f) + a.y * fmaxf(acc.y, 0.f)
                + a.z * fmaxf(acc.z, 0.f) + a.w * fmaxf(acc.w, 0.f);
        #pragma unroll
        for (int off = 16; off > 0; off >>= 1)
            s += __shfl_xor_sync(0xffffffffu, s, off);
        if (lane == 0) slog[j] = s;
    }
    __syncthreads();

    if (w == 0) {
        float el = -1e30f;
        int p = 0;
        if (lane < 16) {
            int s = senders[14 * DEG + lane];
            for (int j = 0; j < cnt2; j++) if (g_list2[j] == s) p = j;
            el = slog[p];
            spos[lane] = p;
        }
        float m = el;
        #pragma unroll
        for (int off = 8; off > 0; off >>= 1)
            m = fmaxf(m, __shfl_xor_sync(0xffffffffu, m, off));
        float wv = (lane < 16) ? expf(el - m) : 0.f;
        float sum = wv;
        #pragma unroll
        for (int off = 8; off > 0; off >>= 1)
            sum += __shfl_xor_sync(0xffffffffu, sum, off);
        if (lane < 16) sw[lane] = wv;
        if (lane == 0) sinv = 1.f / sum;
    }
    __syncthreads();

    {
        float m = 0.f;
        #pragma unroll
        for (int k = 0; k < 16; k++) m = fmaf(sw[k], hs[spos[k]][tid], m);
        smsg[tid] = m * sinv;
    }
    __syncthreads();

    if (tid < 128) {
        float acc = lb2[tid];
        for (int k = 0; k < 256; k++) acc = fmaf(hs[spos14][k], lw2[k * 128 + tid], acc);
        for (int k = 0; k < 256; k++) acc = fmaf(smsg[k], lw2[(256 + k) * 128 + tid], acc);
        sh3[tid] = fmaxf(acc, 0.f);
    }
    __syncthreads();

    if (tid < 128) {
        float acc = ob[tid];
        #pragma unroll 8
        for (int d = 0; d < 128; d++) acc = fmaf(sh3[d], ow[d * 128 + tid], acc);
        out[tid] = acc;
    }
}

// ---------------- launch ----------------
extern "C" void kernel_launch(void* const* d_in, const int* in_sizes, int n_in,
                              void* d_out, int out_size) {
    const float* X       = (const float*)d_in[0];
    const int*   senders = (const int*)d_in[1];
    const float* lw0 = (const float*)d_in[3];
    const float* lb0 = (const float*)d_in[4];
    const float* aw0 = (const float*)d_in[5];
    const float* aq0 = (const float*)d_in[6];
    const float* lw1 = (const float*)d_in[7];
    const float* lb1 = (const float*)d_in[8];
    const float* aw1 = (const float*)d_in[9];
    const float* aq1 = (const float*)d_in[10];
    const float* lw2 = (const float*)d_in[11];
    const float* lb2 = (const float*)d_in[12];
    const float* aw2 = (const float*)d_in[13];
    const float* aq2 = (const float*)d_in[14];
    const float* ow  = (const float*)d_in[15];
    const float* ob  = (const float*)d_in[16];

    int *l0, *l1, *l2, *cnt, *pos0, *pos1;
    float *hN, *lpart, *partT, *wt0, *wtL, *wt1, *wtL1, *h1;
    cudaGetSymbolAddress((void**)&l0, g_list0);
    cudaGetSymbolAddress((void**)&l1, g_list1);
    cudaGetSymbolAddress((void**)&l2, g_list2);
    cudaGetSymbolAddress((void**)&cnt, g_cnt);
    cudaGetSymbolAddress((void**)&pos0, g_pos0);
    cudaGetSymbolAddress((void**)&pos1, g_pos1);
    cudaGetSymbolAddress((void**)&hN, g_hN);
    cudaGetSymbolAddress((void**)&lpart, g_lpart);
    cudaGetSymbolAddress((void**)&partT, g_partT);
    cudaGetSymbolAddress((void**)&wt0, g_wt0);
    cudaGetSymbolAddress((void**)&wtL, g_wtL);
    cudaGetSymbolAddress((void**)&wt1, g_wt1);
    cudaGetSymbolAddress((void**)&wtL1, g_wtL1);
    cudaGetSymbolAddress((void**)&h1, g_h1);

    cone_kernel<<<1, 1024>>>(senders);
    transpose_all_kernel<<<dim3(64, 16, 4), dim3(32, 8)>>>(aw0, lw0, aw1, lw1);

    // ---- layer 0: din=1024, dh=512 ----
    mma_gemm_kernel<0><<<dim3(39, 4, 1), 256>>>(
        X, nullptr, wt0, aq0, lpart, l0, cnt + 0, 1024, 1024, 1024, 0, 0);
    attn_kernel<<<dim3(289, 4), 256>>>(X, lpart, pos0, senders, l1, cnt + 1, hN, 1024, 4);
    mma_gemm_kernel<1><<<dim3(3, 4, 8), 256>>>(
        X, hN, wtL, nullptr, partT, l1, cnt + 1, 1024, 2048, 256, 3, 512);
    tlinear_reduce_kernel<<<289, 256>>>(partT, lb0, h1, l1, cnt + 1, 8, 3, 512);

    // ---- layer 1: din=512, dh=256 ----
    mma_gemm_kernel<0><<<dim3(3, 2, 1), 256>>>(
        h1, nullptr, wt1, aq1, lpart, l1, cnt + 1, 512, 512, 512, 0, 0);
    attn_kernel<<<dim3(17, 2), 256>>>(h1, lpart, pos1, senders, l2, cnt + 2, hN, 512, 2);
    mma_gemm_kernel<1><<<dim3(1, 2, 2), 256>>>(
        h1, hN, wtL1, nullptr, partT, l2, cnt + 2, 512, 1024, 512, 1, 256);

    // ---- fused tlinear_reduce1 + layer 2 + output head ----
    layer2_out_kernel<<<1, 256>>>(partT, lb1, senders, aw2, aq2, lw2, lb2,
                                  ow, ob, (float*)d_out, 2);
}